// round 1
// baseline (speedup 1.0000x reference)
#include <cuda_runtime.h>
#include <cstdint>

// HashGridEncoding: 16 levels, 2 feats/level, T = 2^19, base_res 16, scale 1.5,
// fused with Linear(32 -> 64).
// Inputs (metadata order): x [8,131072,3] f32, table [16,524288,2] f32,
//                          W [64,32] f32, b [64] f32.
// Output: [8,131072,64] f32.

#define NLEVELS 16
#define TSIZE   (1u << 19)

// scale_l = 16*1.5^l - 1 computed exactly in double, rounded to f32 (matches
// XLA converting the python-float scalar to f32 before the multiply).
__device__ __forceinline__ uint32_t umin32(uint32_t a, uint32_t b) { return a < b ? a : b; }

__global__ __launch_bounds__(128)
void hashgrid_fused_kernel(const float* __restrict__ x,
                           const float* __restrict__ table,
                           const float* __restrict__ W,
                           const float* __restrict__ bias,
                           float* __restrict__ out,
                           int P)
{
    __shared__ float sW[64 * 32];      // 8 KB, row-major [out=64][in=32]
    __shared__ float sB[64];
    __shared__ float sOut[128 * 33];   // padded stride 33 -> conflict-free transpose

    const int tid = threadIdx.x;

    // Cooperative load of W + b into shared (overlaps with gather phase below;
    // __syncthreads sits after the encode loop).
    #pragma unroll
    for (int i = 0; i < 16; ++i) sW[tid + 128 * i] = W[tid + 128 * i];
    if (tid < 64) sB[tid] = bias[tid];

    const int p  = blockIdx.x * 128 + tid;
    const int pc = (p < P) ? p : (P - 1);   // clamp so every thread can sync

    // ---- load point, normalize [-1,1] -> [0,1] (match ref op order, no fma) ----
    const float xin = x[3 * pc + 0];
    const float yin = x[3 * pc + 1];
    const float zin = x[3 * pc + 2];
    const float xn = __fmul_rn(__fadd_rn(xin, 1.0f), 0.5f);
    const float yn = __fmul_rn(__fadd_rn(yin, 1.0f), 0.5f);
    const float zn = __fmul_rn(__fadd_rn(zin, 1.0f), 0.5f);

    const float SCALES[NLEVELS] = {
        15.0f, 23.0f, 35.0f, 53.0f, 80.0f, 120.5f, 181.25f, 272.375f,
        409.0625f, 614.09375f, 921.640625f, 1382.9609375f,
        2074.94140625f, 3112.912109375f, 4669.8681640625f, 7005.30224609375f };
    const uint32_t RES_D[4] = { 16u, 24u, 36u, 54u };   // levels 0..3 dense (res^3 <= T)

    float enc[32];

    #pragma unroll
    for (int l = 0; l < NLEVELS; ++l) {
        const float s = SCALES[l];
        const float px = __fadd_rn(__fmul_rn(xn, s), 0.5f);
        const float py = __fadd_rn(__fmul_rn(yn, s), 0.5f);
        const float pz = __fadd_rn(__fmul_rn(zn, s), 0.5f);
        const float fx0 = floorf(px), fy0 = floorf(py), fz0 = floorf(pz);
        const float fx = __fadd_rn(px, -fx0);
        const float fy = __fadd_rn(py, -fy0);
        const float fz = __fadd_rn(pz, -fz0);
        const uint32_t x0 = (uint32_t)fx0;
        const uint32_t y0 = (uint32_t)fy0;
        const uint32_t z0 = (uint32_t)fz0;

        uint32_t ix[2], iy[2], iz[2];
        if (l < 4) {
            const uint32_t R = RES_D[l];
            ix[0] = umin32(x0,      R - 1u);
            ix[1] = umin32(x0 + 1u, R - 1u);
            iy[0] = umin32(y0,      R - 1u) * R;
            iy[1] = umin32(y0 + 1u, R - 1u) * R;
            iz[0] = umin32(z0,      R - 1u) * (R * R);
            iz[1] = umin32(z0 + 1u, R - 1u) * (R * R);
        } else {
            ix[0] = x0;
            ix[1] = x0 + 1u;
            iy[0] = y0 * 2654435761u;
            iy[1] = iy[0] + 2654435761u;
            iz[0] = z0 * 805459861u;
            iz[1] = iz[0] + 805459861u;
        }

        const float wx[2] = { 1.0f - fx, fx };
        const float wy[2] = { 1.0f - fy, fy };
        const float wz[2] = { 1.0f - fz, fz };

        const float2* __restrict__ tl =
            reinterpret_cast<const float2*>(table) + (size_t)l * TSIZE;

        // Precompute all 8 indices + weights, issue all 8 loads (high MLP),
        // then accumulate.
        uint32_t idx8[8];
        float    w8[8];
        #pragma unroll
        for (int ci = 0; ci < 2; ++ci)
            #pragma unroll
            for (int cj = 0; cj < 2; ++cj)
                #pragma unroll
                for (int ck = 0; ck < 2; ++ck) {
                    const int r = ci * 4 + cj * 2 + ck;
                    uint32_t idx;
                    if (l < 4) idx = ix[ci] + iy[cj] + iz[ck];
                    else       idx = (ix[ci] ^ iy[cj] ^ iz[ck]) & (TSIZE - 1u);
                    idx8[r] = idx;
                    w8[r]   = wx[ci] * wy[cj] * wz[ck];
                }
        float2 v8[8];
        #pragma unroll
        for (int r = 0; r < 8; ++r) v8[r] = __ldg(tl + idx8[r]);

        float a0 = 0.0f, a1 = 0.0f;
        #pragma unroll
        for (int r = 0; r < 8; ++r) {
            a0 = fmaf(w8[r], v8[r].x, a0);
            a1 = fmaf(w8[r], v8[r].y, a1);
        }
        enc[2 * l + 0] = a0;
        enc[2 * l + 1] = a1;
    }

    __syncthreads();   // W/b ready; also fences sOut usage

    // ---- fused Linear(32 -> 64), in two halves of 32 outputs ----
    const int pBase = blockIdx.x * 128;
    #pragma unroll 1
    for (int h = 0; h < 2; ++h) {
        #pragma unroll
        for (int j = 0; j < 32; ++j) {
            const float4* wr = reinterpret_cast<const float4*>(&sW[(h * 32 + j) * 32]);
            float a = sB[h * 32 + j];
            #pragma unroll
            for (int kk = 0; kk < 8; ++kk) {
                const float4 wv = wr[kk];   // broadcast LDS.128 (uniform addr)
                a = fmaf(enc[4 * kk + 0], wv.x, a);
                a = fmaf(enc[4 * kk + 1], wv.y, a);
                a = fmaf(enc[4 * kk + 2], wv.z, a);
                a = fmaf(enc[4 * kk + 3], wv.w, a);
            }
            sOut[tid * 33 + j] = a;         // bank = (tid + j) % 32: conflict-free
        }
        __syncthreads();
        // Coalesced write-out: each warp iteration writes one point's 32
        // consecutive floats (128 B contiguous per warp).
        #pragma unroll
        for (int it = 0; it < 32; ++it) {
            const int idx = it * 128 + tid;
            const int pl  = idx >> 5;
            const int j   = idx & 31;
            const int gp  = pBase + pl;
            if (gp < P)
                out[(size_t)gp * 64 + h * 32 + j] = sOut[pl * 33 + j];
        }
        __syncthreads();
    }
}

extern "C" void kernel_launch(void* const* d_in, const int* in_sizes, int n_in,
                              void* d_out, int out_size)
{
    const float* x     = (const float*)d_in[0];
    const float* table = (const float*)d_in[1];
    const float* W     = (const float*)d_in[2];
    const float* b     = (const float*)d_in[3];
    float* out = (float*)d_out;

    const int P    = in_sizes[0] / 3;          // 1,048,576 points
    const int grid = (P + 127) / 128;
    hashgrid_fused_kernel<<<grid, 128>>>(x, table, W, b, out, P);
}

// round 2
// speedup vs baseline: 1.0351x; 1.0351x over previous
#include <cuda_runtime.h>
#include <cstdint>

// HashGridEncoding (16 levels, F=2, T=2^19, base 16, scale 1.5) fused with
// Linear(32 -> 64).  x:[8,131072,3] f32, table:[16,524288,2] f32,
// W:[64,32] f32, b:[64] f32 -> out:[8,131072,64] f32.

#define NLEVELS 16
#define TSIZE   (1u << 19)
#define TMASK   (TSIZE - 1u)
#define P1      2654435761u
#define P2      805459861u

__device__ __forceinline__ uint32_t umin32(uint32_t a, uint32_t b) { return a < b ? a : b; }

__global__ __launch_bounds__(128, 4)
void hashgrid_fused_kernel(const float* __restrict__ x,
                           const float* __restrict__ table,
                           const float* __restrict__ W,
                           const float* __restrict__ bias,
                           float* __restrict__ out,
                           int P)
{
    // enc staging: point-major, stride 17 float2 (34 words, 2-way STS conflict,
    // conflict-free-enough; reads are uniform broadcasts).
    __shared__ float2 sEnc[128 * 17];

    const int tid = threadIdx.x;
    const int p   = blockIdx.x * 128 + tid;
    const int pc  = (p < P) ? p : (P - 1);

    // ---- load point, normalize [-1,1] -> [0,1] ----
    const float xn = __fmul_rn(__fadd_rn(x[3 * pc + 0], 1.0f), 0.5f);
    const float yn = __fmul_rn(__fadd_rn(x[3 * pc + 1], 1.0f), 0.5f);
    const float zn = __fmul_rn(__fadd_rn(x[3 * pc + 2], 1.0f), 0.5f);

    const float SCALES[NLEVELS] = {
        15.0f, 23.0f, 35.0f, 53.0f, 80.0f, 120.5f, 181.25f, 272.375f,
        409.0625f, 614.09375f, 921.640625f, 1382.9609375f,
        2074.94140625f, 3112.912109375f, 4669.8681640625f, 7005.30224609375f };
    const uint32_t RES_D[4] = { 16u, 24u, 36u, 54u };   // levels 0..3 dense

    const float2* __restrict__ tbl2 = reinterpret_cast<const float2*>(table);
    const float4* __restrict__ tbl4 = reinterpret_cast<const float4*>(table);

    #pragma unroll
    for (int l = 0; l < NLEVELS; ++l) {
        const float s  = SCALES[l];
        const float px = __fadd_rn(__fmul_rn(xn, s), 0.5f);
        const float py = __fadd_rn(__fmul_rn(yn, s), 0.5f);
        const float pz = __fadd_rn(__fmul_rn(zn, s), 0.5f);
        const float fx0 = floorf(px), fy0 = floorf(py), fz0 = floorf(pz);
        const float fx = __fadd_rn(px, -fx0);
        const float fy = __fadd_rn(py, -fy0);
        const float fz = __fadd_rn(pz, -fz0);
        const uint32_t x0 = (uint32_t)fx0;
        const uint32_t y0 = (uint32_t)fy0;
        const uint32_t z0 = (uint32_t)fz0;

        const float wx0 = 1.0f - fx, wx1 = fx;
        const float wy0 = 1.0f - fy, wy1 = fy;
        const float wz0 = 1.0f - fz, wz1 = fz;

        float a0 = 0.0f, a1 = 0.0f;

        if (l < 4) {
            // ---- dense level: stride indexing, clamped ----
            const uint32_t R = RES_D[l];
            uint32_t ix[2], iy[2], iz[2];
            ix[0] = umin32(x0,      R - 1u);
            ix[1] = umin32(x0 + 1u, R - 1u);
            iy[0] = umin32(y0,      R - 1u) * R;
            iy[1] = umin32(y0 + 1u, R - 1u) * R;
            iz[0] = umin32(z0,      R - 1u) * (R * R);
            iz[1] = umin32(z0 + 1u, R - 1u) * (R * R);
            const float wxv[2] = { wx0, wx1 };
            const float wyv[2] = { wy0, wy1 };
            const float wzv[2] = { wz0, wz1 };

            uint32_t idx8[8];
            float    w8[8];
            #pragma unroll
            for (int ci = 0; ci < 2; ++ci)
                #pragma unroll
                for (int cj = 0; cj < 2; ++cj)
                    #pragma unroll
                    for (int ck = 0; ck < 2; ++ck) {
                        const int r = ci * 4 + cj * 2 + ck;
                        idx8[r] = ix[ci] + iy[cj] + iz[ck];
                        w8[r]   = wxv[ci] * wyv[cj] * wzv[ck];
                    }
            float2 v8[8];
            const float2* tl = tbl2 + (size_t)l * TSIZE;
            #pragma unroll
            for (int r = 0; r < 8; ++r) v8[r] = __ldg(tl + idx8[r]);
            #pragma unroll
            for (int r = 0; r < 8; ++r) {
                a0 = fmaf(w8[r], v8[r].x, a0);
                a1 = fmaf(w8[r], v8[r].y, a1);
            }
        } else {
            // ---- hashed level with x-corner pairing ----
            // x-prime is 1, so when x0 is even the two x-corners are table
            // entries i0 and i0^1: one aligned float4 fetches both.
            const uint32_t hy0 = y0 * P1;
            const uint32_t hy1 = hy0 + P1;
            const uint32_t hz0 = z0 * P2;
            const uint32_t hz1 = hz0 + P2;
            const uint32_t x1  = x0 + 1u;
            const bool xodd = (x0 & 1u) != 0u;

            const uint32_t hyz[4] = { hy0 ^ hz0, hy0 ^ hz1, hy1 ^ hz0, hy1 ^ hz1 };
            const float    wyz[4] = { wy0 * wz0, wy0 * wz1, wy1 * wz0, wy1 * wz1 };

            const float2* tl2 = tbl2 + (size_t)l * TSIZE;
            const float4* tl4 = tbl4 + (size_t)l * (TSIZE / 2);

            uint32_t i0s[4];
            #pragma unroll
            for (int r = 0; r < 4; ++r) i0s[r] = (x0 ^ hyz[r]) & TMASK;

            float4 v4[4];
            #pragma unroll
            for (int r = 0; r < 4; ++r) v4[r] = __ldg(tl4 + (i0s[r] >> 1));

            float2 vb[4];
            if (xodd) {
                #pragma unroll
                for (int r = 0; r < 4; ++r)
                    vb[r] = __ldg(tl2 + ((x1 ^ hyz[r]) & TMASK));
            }

            #pragma unroll
            for (int r = 0; r < 4; ++r) {
                const bool hi = (i0s[r] & 1u) != 0u;
                // c0 = feat(i0): half of v4 selected by bit0(i0)
                const float c0x = hi ? v4[r].z : v4[r].x;
                const float c0y = hi ? v4[r].w : v4[r].y;
                // c1 = feat((x0+1)^hyz): other half when x0 even, else vb
                const float ox  = hi ? v4[r].x : v4[r].z;
                const float oy  = hi ? v4[r].y : v4[r].w;
                const float c1x = xodd ? vb[r].x : ox;
                const float c1y = xodd ? vb[r].y : oy;

                const float w0 = wx0 * wyz[r];
                const float w1 = wx1 * wyz[r];
                a0 = fmaf(w0, c0x, a0);
                a1 = fmaf(w0, c0y, a1);
                a0 = fmaf(w1, c1x, a0);
                a1 = fmaf(w1, c1y, a1);
            }
        }

        sEnc[tid * 17 + l] = make_float2(a0, a1);
    }

    __syncwarp();   // enc of this warp's points visible to this warp

    // ---- Linear(32 -> 64): lane j computes outputs j and j+32 for the
    //      warp's own 32 points; enc read as uniform LDS.64 broadcasts. ----
    const int lane  = tid & 31;
    const int wbase = tid & ~31;                       // warp's first local point
    const int gbase = blockIdx.x * 128 + wbase;

    const float4* __restrict__ W4 = reinterpret_cast<const float4*>(W);
    float4 wa[8], wb[8];
    #pragma unroll
    for (int q = 0; q < 8; ++q) {
        wa[q] = __ldg(W4 + lane * 8 + q);
        wb[q] = __ldg(W4 + (lane + 32) * 8 + q);
    }
    const float bA = __ldg(bias + lane);
    const float bB = __ldg(bias + lane + 32);
    const float* wAf = reinterpret_cast<const float*>(wa);
    const float* wBf = reinterpret_cast<const float*>(wb);

    #pragma unroll 1
    for (int q = 0; q < 32; ++q) {
        const float2* e = &sEnc[(wbase + q) * 17];
        float aA = bA, aB = bB;
        #pragma unroll
        for (int l = 0; l < 16; ++l) {
            const float2 ev = e[l];                    // uniform broadcast
            aA = fmaf(ev.x, wAf[2 * l + 0], aA);
            aA = fmaf(ev.y, wAf[2 * l + 1], aA);
            aB = fmaf(ev.x, wBf[2 * l + 0], aB);
            aB = fmaf(ev.y, wBf[2 * l + 1], aB);
        }
        const int gp = gbase + q;
        if (gp < P) {
            out[(size_t)gp * 64 + lane]      = aA;     // 128B coalesced
            out[(size_t)gp * 64 + 32 + lane] = aB;     // 128B coalesced
        }
    }
}

extern "C" void kernel_launch(void* const* d_in, const int* in_sizes, int n_in,
                              void* d_out, int out_size)
{
    const float* x     = (const float*)d_in[0];
    const float* table = (const float*)d_in[1];
    const float* W     = (const float*)d_in[2];
    const float* b     = (const float*)d_in[3];
    float* out = (float*)d_out;

    const int P    = in_sizes[0] / 3;          // 1,048,576 points
    const int grid = (P + 127) / 128;
    hashgrid_fused_kernel<<<grid, 128>>>(x, table, W, b, out, P);
}

// round 3
// speedup vs baseline: 1.0666x; 1.0305x over previous
#include <cuda_runtime.h>
#include <cstdint>

// HashGridEncoding (16 levels, F=2, T=2^19, base 16, scale 1.5) fused with
// Linear(32 -> 64).  x:[8,131072,3] f32, table:[16,524288,2] f32,
// W:[64,32] f32, b:[64] f32 -> out:[8,131072,64] f32.

#define NLEVELS 16
#define TSIZE   (1u << 19)
#define TMASK   (TSIZE - 1u)
#define HP1     2654435761u
#define HP2     805459861u

__device__ __forceinline__ uint32_t umin32(uint32_t a, uint32_t b) { return a < b ? a : b; }

__global__ __launch_bounds__(128, 4)
void hashgrid_fused_kernel(const float* __restrict__ x,
                           const float* __restrict__ table,
                           const float* __restrict__ W,
                           const float* __restrict__ bias,
                           float* __restrict__ out,
                           int P)
{
    // enc staging: point-major float4 (levels 2k,2k+1), stride 9 float4.
    // STS.128: 16B-bank = (9*tid + k) & 7 -> conflict-free.
    // Reads are uniform LDS.128 broadcasts (1 wavefront each).
    __shared__ float4 sEnc[128 * 9];

    const int tid = threadIdx.x;
    const int p   = blockIdx.x * 128 + tid;
    const int pc  = (p < P) ? p : (P - 1);

    // ---- load point, normalize [-1,1] -> [0,1] ----
    const float xn = __fmul_rn(__fadd_rn(x[3 * pc + 0], 1.0f), 0.5f);
    const float yn = __fmul_rn(__fadd_rn(x[3 * pc + 1], 1.0f), 0.5f);
    const float zn = __fmul_rn(__fadd_rn(x[3 * pc + 2], 1.0f), 0.5f);

    const float SCALES[NLEVELS] = {
        15.0f, 23.0f, 35.0f, 53.0f, 80.0f, 120.5f, 181.25f, 272.375f,
        409.0625f, 614.09375f, 921.640625f, 1382.9609375f,
        2074.94140625f, 3112.912109375f, 4669.8681640625f, 7005.30224609375f };
    const uint32_t RES_D[4] = { 16u, 24u, 36u, 54u };   // levels 0..3 dense

    const float2* __restrict__ tbl2 = reinterpret_cast<const float2*>(table);
    const float4* __restrict__ tbl4 = reinterpret_cast<const float4*>(table);

    float keep0 = 0.0f, keep1 = 0.0f;   // even-level result held for paired STS.128

    #pragma unroll
    for (int l = 0; l < NLEVELS; ++l) {
        const float s  = SCALES[l];
        const float px = __fadd_rn(__fmul_rn(xn, s), 0.5f);
        const float py = __fadd_rn(__fmul_rn(yn, s), 0.5f);
        const float pz = __fadd_rn(__fmul_rn(zn, s), 0.5f);
        const float fx0 = floorf(px), fy0 = floorf(py), fz0 = floorf(pz);
        const float fx = __fadd_rn(px, -fx0);
        const float fy = __fadd_rn(py, -fy0);
        const float fz = __fadd_rn(pz, -fz0);
        const uint32_t x0 = (uint32_t)fx0;
        const uint32_t y0 = (uint32_t)fy0;
        const uint32_t z0 = (uint32_t)fz0;

        const float wx0 = 1.0f - fx, wx1 = fx;
        const float wy0 = 1.0f - fy, wy1 = fy;
        const float wz0 = 1.0f - fz, wz1 = fz;

        float a0 = 0.0f, a1 = 0.0f;
        const bool xodd = (x0 & 1u) != 0u;

        if (l < 4) {
            // ---- dense level: stride indexing, clamped, x-corner pairing ----
            // R even => parity(idx0) = parity(cx0); two x-corners are idx0, idx0+1.
            const uint32_t R  = RES_D[l];
            const uint32_t cx0 = umin32(x0, R - 1u);
            const bool d1   = (x0 < R - 1u);            // x-corner 1 distinct?
            const uint32_t iy0 = umin32(y0,      R - 1u) * R;
            const uint32_t iy1 = umin32(y0 + 1u, R - 1u) * R;
            const uint32_t iz0 = umin32(z0,      R - 1u) * (R * R);
            const uint32_t iz1 = umin32(z0 + 1u, R - 1u) * (R * R);

            const uint32_t byz[4] = { iy0 + iz0, iy0 + iz1, iy1 + iz0, iy1 + iz1 };
            const float    wyz[4] = { wy0 * wz0, wy0 * wz1, wy1 * wz0, wy1 * wz1 };

            const float2* tl2 = tbl2 + (size_t)l * TSIZE;
            const float4* tl4 = tbl4 + (size_t)l * (TSIZE / 2);

            uint32_t i0s[4];
            #pragma unroll
            for (int r = 0; r < 4; ++r) i0s[r] = cx0 + byz[r];

            float4 v4[4];
            #pragma unroll
            for (int r = 0; r < 4; ++r) v4[r] = __ldg(tl4 + (i0s[r] >> 1));

            const bool need2 = d1 && xodd;              // idx0 odd & unclamped
            float2 vb[4];
            if (need2) {
                #pragma unroll
                for (int r = 0; r < 4; ++r) vb[r] = __ldg(tl2 + (i0s[r] + 1u));
            }

            #pragma unroll
            for (int r = 0; r < 4; ++r) {
                const bool hi = (i0s[r] & 1u) != 0u;
                const float c0x = hi ? v4[r].z : v4[r].x;
                const float c0y = hi ? v4[r].w : v4[r].y;
                const float ox  = hi ? vb[r].x : v4[r].z;   // hi: extra load; !hi: high half
                const float oy  = hi ? vb[r].y : v4[r].w;
                const float c1x = d1 ? ox : c0x;            // clamped: c1 == c0
                const float c1y = d1 ? oy : c0y;

                const float w0 = wx0 * wyz[r];
                const float w1 = wx1 * wyz[r];
                a0 = fmaf(w0, c0x, a0);
                a1 = fmaf(w0, c0y, a1);
                a0 = fmaf(w1, c1x, a0);
                a1 = fmaf(w1, c1y, a1);
            }
        } else {
            // ---- hashed level: x-prime = 1, x-corner pairing ----
            const uint32_t hy0 = y0 * HP1;
            const uint32_t hy1 = hy0 + HP1;
            const uint32_t hz0 = z0 * HP2;
            const uint32_t hz1 = hz0 + HP2;
            const uint32_t x1  = x0 + 1u;

            const uint32_t hyz[4] = { hy0 ^ hz0, hy0 ^ hz1, hy1 ^ hz0, hy1 ^ hz1 };
            const float    wyz[4] = { wy0 * wz0, wy0 * wz1, wy1 * wz0, wy1 * wz1 };

            const float2* tl2 = tbl2 + (size_t)l * TSIZE;
            const float4* tl4 = tbl4 + (size_t)l * (TSIZE / 2);

            uint32_t i0s[4];
            #pragma unroll
            for (int r = 0; r < 4; ++r) i0s[r] = (x0 ^ hyz[r]) & TMASK;

            float4 v4[4];
            #pragma unroll
            for (int r = 0; r < 4; ++r) v4[r] = __ldg(tl4 + (i0s[r] >> 1));

            float2 vb[4];
            if (xodd) {
                #pragma unroll
                for (int r = 0; r < 4; ++r)
                    vb[r] = __ldg(tl2 + ((x1 ^ hyz[r]) & TMASK));
            }

            #pragma unroll
            for (int r = 0; r < 4; ++r) {
                const bool hi = (i0s[r] & 1u) != 0u;
                const float c0x = hi ? v4[r].z : v4[r].x;
                const float c0y = hi ? v4[r].w : v4[r].y;
                const float ox  = hi ? v4[r].x : v4[r].z;
                const float oy  = hi ? v4[r].y : v4[r].w;
                const float c1x = xodd ? vb[r].x : ox;
                const float c1y = xodd ? vb[r].y : oy;

                const float w0 = wx0 * wyz[r];
                const float w1 = wx1 * wyz[r];
                a0 = fmaf(w0, c0x, a0);
                a1 = fmaf(w0, c0y, a1);
                a0 = fmaf(w1, c1x, a0);
                a1 = fmaf(w1, c1y, a1);
            }
        }

        if ((l & 1) == 0) {
            keep0 = a0; keep1 = a1;
        } else {
            sEnc[tid * 9 + (l >> 1)] = make_float4(keep0, keep1, a0, a1);
        }
    }

    __syncwarp();   // this warp's enc visible to this warp

    // ---- Linear(32 -> 64): lane j computes outputs j and j+32 for the
    //      warp's own 32 points; enc read as uniform LDS.128 broadcasts. ----
    const int lane  = tid & 31;
    const int wbase = tid & ~31;
    const int gbase = blockIdx.x * 128 + wbase;

    const float4* __restrict__ W4 = reinterpret_cast<const float4*>(W);
    float4 wa[8], wb[8];
    #pragma unroll
    for (int q = 0; q < 8; ++q) {
        wa[q] = __ldg(W4 + lane * 8 + q);
        wb[q] = __ldg(W4 + (lane + 32) * 8 + q);
    }
    const float bA = __ldg(bias + lane);
    const float bB = __ldg(bias + lane + 32);

    #pragma unroll 1
    for (int q = 0; q < 32; ++q) {
        const float4* e = &sEnc[(wbase + q) * 9];
        float aA = bA, aB = bB;
        #pragma unroll
        for (int k = 0; k < 8; ++k) {
            const float4 ev = e[k];                    // uniform LDS.128 broadcast
            aA = fmaf(ev.x, wa[k].x, aA);
            aA = fmaf(ev.y, wa[k].y, aA);
            aA = fmaf(ev.z, wa[k].z, aA);
            aA = fmaf(ev.w, wa[k].w, aA);
            aB = fmaf(ev.x, wb[k].x, aB);
            aB = fmaf(ev.y, wb[k].y, aB);
            aB = fmaf(ev.z, wb[k].z, aB);
            aB = fmaf(ev.w, wb[k].w, aB);
        }
        const int gp = gbase + q;
        if (gp < P) {
            out[(size_t)gp * 64 + lane]      = aA;     // 128B coalesced
            out[(size_t)gp * 64 + 32 + lane] = aB;     // 128B coalesced
        }
    }
}

extern "C" void kernel_launch(void* const* d_in, const int* in_sizes, int n_in,
                              void* d_out, int out_size)
{
    const float* x     = (const float*)d_in[0];
    const float* table = (const float*)d_in[1];
    const float* W     = (const float*)d_in[2];
    const float* b     = (const float*)d_in[3];
    float* out = (float*)d_out;

    const int P    = in_sizes[0] / 3;          // 1,048,576 points
    const int grid = (P + 127) / 128;
    hashgrid_fused_kernel<<<grid, 128>>>(x, table, W, b, out, P);
}

// round 4
// speedup vs baseline: 1.2184x; 1.1423x over previous
#include <cuda_runtime.h>
#include <cstdint>

// HashGridEncoding (16 levels, F=2, T=2^19, base 16, scale 1.5) fused with
// Linear(32 -> 64).  x:[8,131072,3] f32, table:[16,524288,2] f32,
// W:[64,32] f32, b:[64] f32 -> out:[8,131072,64] f32.

#define NLEVELS 16
#define TSIZE   (1u << 19)
#define TMASK   (TSIZE - 1u)
#define HP1     2654435761u
#define HP2     805459861u

__device__ __forceinline__ uint32_t umin32(uint32_t a, uint32_t b) { return a < b ? a : b; }

__global__ __launch_bounds__(128, 4)
void hashgrid_fused_kernel(const float* __restrict__ x,
                           const float* __restrict__ table,
                           const float* __restrict__ W,
                           const float* __restrict__ bias,
                           float* __restrict__ out,
                           int P)
{
    // enc staging: point-major float4 (levels 2k,2k+1), stride 9 float4.
    __shared__ float4 sEnc[128 * 9];
    // W staged once per block: row r at sW4[r*9 + q], q=0..7 (pad 1 float4).
    // Per-lane row reads are conflict-free in the 8-lane LDS.128 phase model.
    __shared__ float4 sW4[64 * 9];
    __shared__ float  sB[64];

    const int tid = threadIdx.x;

    // ---- cooperative coalesced W/b load (sync before matmul phase) ----
    {
        const float4* __restrict__ Wg = reinterpret_cast<const float4*>(W);
        #pragma unroll
        for (int i = 0; i < 4; ++i) {
            const int g = tid + 128 * i;            // 512 float4 total
            sW4[(g >> 3) * 9 + (g & 7)] = __ldg(Wg + g);
        }
        if (tid < 64) sB[tid] = __ldg(bias + tid);
    }

    const int p  = blockIdx.x * 128 + tid;
    const int pc = (p < P) ? p : (P - 1);

    // ---- load point, normalize [-1,1] -> [0,1] ----
    const float xn = __fmul_rn(__fadd_rn(x[3 * pc + 0], 1.0f), 0.5f);
    const float yn = __fmul_rn(__fadd_rn(x[3 * pc + 1], 1.0f), 0.5f);
    const float zn = __fmul_rn(__fadd_rn(x[3 * pc + 2], 1.0f), 0.5f);

    const float SCALES[NLEVELS] = {
        15.0f, 23.0f, 35.0f, 53.0f, 80.0f, 120.5f, 181.25f, 272.375f,
        409.0625f, 614.09375f, 921.640625f, 1382.9609375f,
        2074.94140625f, 3112.912109375f, 4669.8681640625f, 7005.30224609375f };
    const uint32_t RES_D[4] = { 16u, 24u, 36u, 54u };   // levels 0..3 dense

    const float2* __restrict__ tbl2 = reinterpret_cast<const float2*>(table);
    const float4* __restrict__ tbl4 = reinterpret_cast<const float4*>(table);

    float keep0 = 0.0f, keep1 = 0.0f;

    #pragma unroll
    for (int l = 0; l < NLEVELS; ++l) {
        const float s  = SCALES[l];
        const float px = __fadd_rn(__fmul_rn(xn, s), 0.5f);
        const float py = __fadd_rn(__fmul_rn(yn, s), 0.5f);
        const float pz = __fadd_rn(__fmul_rn(zn, s), 0.5f);
        const float fx0 = floorf(px), fy0 = floorf(py), fz0 = floorf(pz);
        const float fx = __fadd_rn(px, -fx0);
        const float fy = __fadd_rn(py, -fy0);
        const float fz = __fadd_rn(pz, -fz0);
        const uint32_t x0 = (uint32_t)fx0;
        const uint32_t y0 = (uint32_t)fy0;
        const uint32_t z0 = (uint32_t)fz0;

        const float wx0 = 1.0f - fx, wx1 = fx;
        const float wy0 = 1.0f - fy, wy1 = fy;
        const float wz0 = 1.0f - fz, wz1 = fz;

        float a0 = 0.0f, a1 = 0.0f;
        const bool xodd = (x0 & 1u) != 0u;

        if (l < 4) {
            // ---- dense level: stride indexing, clamped, x-corner pairing ----
            const uint32_t R   = RES_D[l];
            const uint32_t cx0 = umin32(x0, R - 1u);
            const bool d1      = (x0 < R - 1u);
            const uint32_t iy0 = umin32(y0,      R - 1u) * R;
            const uint32_t iy1 = umin32(y0 + 1u, R - 1u) * R;
            const uint32_t iz0 = umin32(z0,      R - 1u) * (R * R);
            const uint32_t iz1 = umin32(z0 + 1u, R - 1u) * (R * R);

            const uint32_t byz[4] = { iy0 + iz0, iy0 + iz1, iy1 + iz0, iy1 + iz1 };
            const float    wyz[4] = { wy0 * wz0, wy0 * wz1, wy1 * wz0, wy1 * wz1 };

            const float2* tl2 = tbl2 + (size_t)l * TSIZE;
            const float4* tl4 = tbl4 + (size_t)l * (TSIZE / 2);

            uint32_t i0s[4];
            #pragma unroll
            for (int r = 0; r < 4; ++r) i0s[r] = cx0 + byz[r];

            float4 v4[4];
            #pragma unroll
            for (int r = 0; r < 4; ++r) v4[r] = __ldg(tl4 + (i0s[r] >> 1));

            const bool need2 = d1 && xodd;
            float2 vb[4];
            if (need2) {
                #pragma unroll
                for (int r = 0; r < 4; ++r) vb[r] = __ldg(tl2 + (i0s[r] + 1u));
            }

            #pragma unroll
            for (int r = 0; r < 4; ++r) {
                const bool hi = (i0s[r] & 1u) != 0u;
                const float c0x = hi ? v4[r].z : v4[r].x;
                const float c0y = hi ? v4[r].w : v4[r].y;
                const float ox  = hi ? vb[r].x : v4[r].z;
                const float oy  = hi ? vb[r].y : v4[r].w;
                const float c1x = d1 ? ox : c0x;
                const float c1y = d1 ? oy : c0y;

                const float w0 = wx0 * wyz[r];
                const float w1 = wx1 * wyz[r];
                a0 = fmaf(w0, c0x, a0);
                a1 = fmaf(w0, c0y, a1);
                a0 = fmaf(w1, c1x, a0);
                a1 = fmaf(w1, c1y, a1);
            }
        } else {
            // ---- hashed level: x-prime = 1, x-corner pairing ----
            const uint32_t hy0 = y0 * HP1;
            const uint32_t hy1 = hy0 + HP1;
            const uint32_t hz0 = z0 * HP2;
            const uint32_t hz1 = hz0 + HP2;
            const uint32_t x1  = x0 + 1u;

            const uint32_t hyz[4] = { hy0 ^ hz0, hy0 ^ hz1, hy1 ^ hz0, hy1 ^ hz1 };
            const float    wyz[4] = { wy0 * wz0, wy0 * wz1, wy1 * wz0, wy1 * wz1 };

            const float2* tl2 = tbl2 + (size_t)l * TSIZE;
            const float4* tl4 = tbl4 + (size_t)l * (TSIZE / 2);

            uint32_t i0s[4];
            #pragma unroll
            for (int r = 0; r < 4; ++r) i0s[r] = (x0 ^ hyz[r]) & TMASK;

            float4 v4[4];
            #pragma unroll
            for (int r = 0; r < 4; ++r) v4[r] = __ldg(tl4 + (i0s[r] >> 1));

            float2 vb[4];
            if (xodd) {
                #pragma unroll
                for (int r = 0; r < 4; ++r)
                    vb[r] = __ldg(tl2 + ((x1 ^ hyz[r]) & TMASK));
            }

            #pragma unroll
            for (int r = 0; r < 4; ++r) {
                const bool hi = (i0s[r] & 1u) != 0u;
                const float c0x = hi ? v4[r].z : v4[r].x;
                const float c0y = hi ? v4[r].w : v4[r].y;
                const float ox  = hi ? v4[r].x : v4[r].z;
                const float oy  = hi ? v4[r].y : v4[r].w;
                const float c1x = xodd ? vb[r].x : ox;
                const float c1y = xodd ? vb[r].y : oy;

                const float w0 = wx0 * wyz[r];
                const float w1 = wx1 * wyz[r];
                a0 = fmaf(w0, c0x, a0);
                a1 = fmaf(w0, c0y, a1);
                a0 = fmaf(w1, c1x, a0);
                a1 = fmaf(w1, c1y, a1);
            }
        }

        if ((l & 1) == 0) {
            keep0 = a0; keep1 = a1;
        } else {
            sEnc[tid * 9 + (l >> 1)] = make_float4(keep0, keep1, a0, a1);
        }
    }

    __syncthreads();   // sW4/sB ready; sEnc (per-warp) also ordered

    // ---- Linear(32 -> 64): lane j computes outputs j and j+32 for the
    //      warp's own 32 points. W rows from smem (conflict-free LDS.128),
    //      enc read as uniform LDS.128 broadcasts. ----
    const int lane  = tid & 31;
    const int wbase = tid & ~31;
    const int gbase = blockIdx.x * 128 + wbase;

    float4 wa[8], wb[8];
    #pragma unroll
    for (int q = 0; q < 8; ++q) {
        wa[q] = sW4[lane * 9 + q];
        wb[q] = sW4[(lane + 32) * 9 + q];
    }
    const float bA = sB[lane];
    const float bB = sB[lane + 32];

    #pragma unroll 1
    for (int q = 0; q < 32; ++q) {
        const float4* e = &sEnc[(wbase + q) * 9];
        float aA = bA, aB = bB;
        #pragma unroll
        for (int k = 0; k < 8; ++k) {
            const float4 ev = e[k];                    // uniform LDS.128 broadcast
            aA = fmaf(ev.x, wa[k].x, aA);
            aA = fmaf(ev.y, wa[k].y, aA);
            aA = fmaf(ev.z, wa[k].z, aA);
            aA = fmaf(ev.w, wa[k].w, aA);
            aB = fmaf(ev.x, wb[k].x, aB);
            aB = fmaf(ev.y, wb[k].y, aB);
            aB = fmaf(ev.z, wb[k].z, aB);
            aB = fmaf(ev.w, wb[k].w, aB);
        }
        const int gp = gbase + q;
        if (gp < P) {
            out[(size_t)gp * 64 + lane]      = aA;     // 128B coalesced
            out[(size_t)gp * 64 + 32 + lane] = aB;     // 128B coalesced
        }
    }
}

extern "C" void kernel_launch(void* const* d_in, const int* in_sizes, int n_in,
                              void* d_out, int out_size)
{
    const float* x     = (const float*)d_in[0];
    const float* table = (const float*)d_in[1];
    const float* W     = (const float*)d_in[2];
    const float* b     = (const float*)d_in[3];
    float* out = (float*)d_out;

    const int P    = in_sizes[0] / 3;          // 1,048,576 points
    const int grid = (P + 127) / 128;
    hashgrid_fused_kernel<<<grid, 128>>>(x, table, W, b, out, P);
}

// round 5
// speedup vs baseline: 1.2370x; 1.0152x over previous
#include <cuda_runtime.h>
#include <cstdint>

// HashGridEncoding (16 levels, F=2, T=2^19, base 16, scale 1.5) fused with
// Linear(32 -> 64).  x:[8,131072,3] f32, table:[16,524288,2] f32,
// W:[64,32] f32, b:[64] f32 -> out:[8,131072,64] f32.

#define NLEVELS 16
#define TSIZE   (1u << 19)
#define TMASK   (TSIZE - 1u)
#define HP1     2654435761u
#define HP2     805459861u

__device__ __forceinline__ uint32_t umin32(uint32_t a, uint32_t b) { return a < b ? a : b; }

// packed fp32x2 fma: d = a*b + d (elementwise on two fp32 lanes, exact fp32)
__device__ __forceinline__ void fma2(unsigned long long& d,
                                     unsigned long long a,
                                     unsigned long long b) {
    asm("fma.rn.f32x2 %0, %1, %2, %0;" : "+l"(d) : "l"(a), "l"(b));
}
__device__ __forceinline__ float2 u2f(unsigned long long v) {
    float2 r;
    asm("mov.b64 {%0, %1}, %2;" : "=f"(r.x), "=f"(r.y) : "l"(v));
    return r;
}

__global__ __launch_bounds__(128, 4)
void hashgrid_fused_kernel(const float* __restrict__ x,
                           const float* __restrict__ table,
                           const float* __restrict__ W,
                           const float* __restrict__ bias,
                           float* __restrict__ out,
                           int P)
{
    // enc staging: point-major float4 (levels 2k,2k+1), stride 9 float4.
    __shared__ float4 sEnc[128 * 9];
    // W staged once per block: row r at sW4[r*9 + q], q=0..7 (pad 1 float4).
    __shared__ float4 sW4[64 * 9];
    __shared__ float  sB[64];

    const int tid = threadIdx.x;

    // ---- cooperative coalesced W/b load; sync NOW so warps can later enter
    //      the matmul phase staggered (keeps L1 fed by other warps' gathers) ----
    {
        const float4* __restrict__ Wg = reinterpret_cast<const float4*>(W);
        #pragma unroll
        for (int i = 0; i < 4; ++i) {
            const int g = tid + 128 * i;            // 512 float4 total
            sW4[(g >> 3) * 9 + (g & 7)] = __ldg(Wg + g);
        }
        if (tid < 64) sB[tid] = __ldg(bias + tid);
    }
    __syncthreads();

    const int p  = blockIdx.x * 128 + tid;
    const int pc = (p < P) ? p : (P - 1);

    // ---- load point, normalize [-1,1] -> [0,1] ----
    const float xn = __fmul_rn(__fadd_rn(x[3 * pc + 0], 1.0f), 0.5f);
    const float yn = __fmul_rn(__fadd_rn(x[3 * pc + 1], 1.0f), 0.5f);
    const float zn = __fmul_rn(__fadd_rn(x[3 * pc + 2], 1.0f), 0.5f);

    const float SCALES[NLEVELS] = {
        15.0f, 23.0f, 35.0f, 53.0f, 80.0f, 120.5f, 181.25f, 272.375f,
        409.0625f, 614.09375f, 921.640625f, 1382.9609375f,
        2074.94140625f, 3112.912109375f, 4669.8681640625f, 7005.30224609375f };
    const uint32_t RES_D[4] = { 16u, 24u, 36u, 54u };   // levels 0..3 dense

    const float2* __restrict__ tbl2 = reinterpret_cast<const float2*>(table);
    const float4* __restrict__ tbl4 = reinterpret_cast<const float4*>(table);

    float keep0 = 0.0f, keep1 = 0.0f;

    #pragma unroll
    for (int l = 0; l < NLEVELS; ++l) {
        const float s  = SCALES[l];
        const float px = __fadd_rn(__fmul_rn(xn, s), 0.5f);
        const float py = __fadd_rn(__fmul_rn(yn, s), 0.5f);
        const float pz = __fadd_rn(__fmul_rn(zn, s), 0.5f);
        const float fx0 = floorf(px), fy0 = floorf(py), fz0 = floorf(pz);
        const float fx = __fadd_rn(px, -fx0);
        const float fy = __fadd_rn(py, -fy0);
        const float fz = __fadd_rn(pz, -fz0);
        const uint32_t x0 = (uint32_t)fx0;
        const uint32_t y0 = (uint32_t)fy0;
        const uint32_t z0 = (uint32_t)fz0;

        const float wx0 = 1.0f - fx, wx1 = fx;
        const float wy0 = 1.0f - fy, wy1 = fy;
        const float wz0 = 1.0f - fz, wz1 = fz;

        float a0 = 0.0f, a1 = 0.0f;
        const bool xodd = (x0 & 1u) != 0u;

        if (l < 4) {
            // ---- dense level: stride indexing, clamped, x-corner pairing ----
            const uint32_t R   = RES_D[l];
            const uint32_t cx0 = umin32(x0, R - 1u);
            const bool d1      = (x0 < R - 1u);
            const uint32_t iy0 = umin32(y0,      R - 1u) * R;
            const uint32_t iy1 = umin32(y0 + 1u, R - 1u) * R;
            const uint32_t iz0 = umin32(z0,      R - 1u) * (R * R);
            const uint32_t iz1 = umin32(z0 + 1u, R - 1u) * (R * R);

            const uint32_t byz[4] = { iy0 + iz0, iy0 + iz1, iy1 + iz0, iy1 + iz1 };
            const float    wyz[4] = { wy0 * wz0, wy0 * wz1, wy1 * wz0, wy1 * wz1 };

            const float2* tl2 = tbl2 + (size_t)l * TSIZE;
            const float4* tl4 = tbl4 + (size_t)l * (TSIZE / 2);

            uint32_t i0s[4];
            #pragma unroll
            for (int r = 0; r < 4; ++r) i0s[r] = cx0 + byz[r];

            float4 v4[4];
            #pragma unroll
            for (int r = 0; r < 4; ++r) v4[r] = __ldg(tl4 + (i0s[r] >> 1));

            const bool need2 = d1 && xodd;
            float2 vb[4];
            if (need2) {
                #pragma unroll
                for (int r = 0; r < 4; ++r) vb[r] = __ldg(tl2 + (i0s[r] + 1u));
            }

            #pragma unroll
            for (int r = 0; r < 4; ++r) {
                const bool hi = (i0s[r] & 1u) != 0u;
                const float c0x = hi ? v4[r].z : v4[r].x;
                const float c0y = hi ? v4[r].w : v4[r].y;
                const float ox  = hi ? vb[r].x : v4[r].z;
                const float oy  = hi ? vb[r].y : v4[r].w;
                const float c1x = d1 ? ox : c0x;
                const float c1y = d1 ? oy : c0y;

                const float w0 = wx0 * wyz[r];
                const float w1 = wx1 * wyz[r];
                a0 = fmaf(w0, c0x, a0);
                a1 = fmaf(w0, c0y, a1);
                a0 = fmaf(w1, c1x, a0);
                a1 = fmaf(w1, c1y, a1);
            }
        } else {
            // ---- hashed level: x-prime = 1, x-corner pairing ----
            const uint32_t hy0 = y0 * HP1;
            const uint32_t hy1 = hy0 + HP1;
            const uint32_t hz0 = z0 * HP2;
            const uint32_t hz1 = hz0 + HP2;
            const uint32_t x1  = x0 + 1u;

            const uint32_t hyz[4] = { hy0 ^ hz0, hy0 ^ hz1, hy1 ^ hz0, hy1 ^ hz1 };
            const float    wyz[4] = { wy0 * wz0, wy0 * wz1, wy1 * wz0, wy1 * wz1 };

            const float2* tl2 = tbl2 + (size_t)l * TSIZE;
            const float4* tl4 = tbl4 + (size_t)l * (TSIZE / 2);

            uint32_t i0s[4];
            #pragma unroll
            for (int r = 0; r < 4; ++r) i0s[r] = (x0 ^ hyz[r]) & TMASK;

            float4 v4[4];
            #pragma unroll
            for (int r = 0; r < 4; ++r) v4[r] = __ldg(tl4 + (i0s[r] >> 1));

            float2 vb[4];
            if (xodd) {
                #pragma unroll
                for (int r = 0; r < 4; ++r)
                    vb[r] = __ldg(tl2 + ((x1 ^ hyz[r]) & TMASK));
            }

            #pragma unroll
            for (int r = 0; r < 4; ++r) {
                const bool hi = (i0s[r] & 1u) != 0u;
                const float c0x = hi ? v4[r].z : v4[r].x;
                const float c0y = hi ? v4[r].w : v4[r].y;
                const float ox  = hi ? v4[r].x : v4[r].z;
                const float oy  = hi ? v4[r].y : v4[r].w;
                const float c1x = xodd ? vb[r].x : ox;
                const float c1y = xodd ? vb[r].y : oy;

                const float w0 = wx0 * wyz[r];
                const float w1 = wx1 * wyz[r];
                a0 = fmaf(w0, c0x, a0);
                a1 = fmaf(w0, c0y, a1);
                a0 = fmaf(w1, c1x, a0);
                a1 = fmaf(w1, c1y, a1);
            }
        }

        if ((l & 1) == 0) {
            keep0 = a0; keep1 = a1;
        } else {
            sEnc[tid * 9 + (l >> 1)] = make_float4(keep0, keep1, a0, a1);
        }
    }

    __syncwarp();   // sEnc is per-warp: only warp-level ordering needed

    // ---- Linear(32 -> 64) with packed fp32x2 FMA.
    //      Lane j computes outputs j and j+32 for the warp's 32 points.
    //      enc chunks read as LDS.128 -> two packed (k,k+1) fp32 pairs;
    //      W rows reinterpret as packed pairs; accumulators keep even/odd-k
    //      partial sums per fp32 lane, combined at the end (exact fp32). ----
    const int lane  = tid & 31;
    const int wbase = tid & ~31;
    const int gbase = blockIdx.x * 128 + wbase;

    const ulonglong2* __restrict__ sWp = reinterpret_cast<const ulonglong2*>(sW4);
    ulonglong2 wa[8], wb[8];
    #pragma unroll
    for (int q = 0; q < 8; ++q) {
        wa[q] = sWp[lane * 9 + q];
        wb[q] = sWp[(lane + 32) * 9 + q];
    }
    const float bA = sB[lane];
    const float bB = sB[lane + 32];

    #pragma unroll 1
    for (int q = 0; q < 32; ++q) {
        const ulonglong2* e =
            reinterpret_cast<const ulonglong2*>(&sEnc[(wbase + q) * 9]);
        unsigned long long A0 = 0ull, A1 = 0ull, B0 = 0ull, B1 = 0ull;
        #pragma unroll
        for (int k = 0; k < 8; ++k) {
            const ulonglong2 ev = e[k];        // uniform LDS.128 broadcast
            fma2(A0, ev.x, wa[k].x);
            fma2(A1, ev.y, wa[k].y);
            fma2(B0, ev.x, wb[k].x);
            fma2(B1, ev.y, wb[k].y);
        }
        const float2 fa0 = u2f(A0), fa1 = u2f(A1);
        const float2 fb0 = u2f(B0), fb1 = u2f(B1);
        const float aA = bA + fa0.x + fa0.y + fa1.x + fa1.y;
        const float aB = bB + fb0.x + fb0.y + fb1.x + fb1.y;

        const int gp = gbase + q;
        if (gp < P) {
            out[(size_t)gp * 64 + lane]      = aA;     // 128B coalesced
            out[(size_t)gp * 64 + 32 + lane] = aB;     // 128B coalesced
        }
    }
}

extern "C" void kernel_launch(void* const* d_in, const int* in_sizes, int n_in,
                              void* d_out, int out_size)
{
    const float* x     = (const float*)d_in[0];
    const float* table = (const float*)d_in[1];
    const float* W     = (const float*)d_in[2];
    const float* b     = (const float*)d_in[3];
    float* out = (float*)d_out;

    const int P    = in_sizes[0] / 3;          // 1,048,576 points
    const int grid = (P + 127) / 128;
    hashgrid_fused_kernel<<<grid, 128>>>(x, table, W, b, out, P);
}

// round 6
// speedup vs baseline: 1.2477x; 1.0087x over previous
#include <cuda_runtime.h>
#include <cstdint>

// HashGridEncoding (16 levels, F=2, T=2^19, base 16, scale 1.5) fused with
// Linear(32 -> 64).  x:[8,131072,3] f32, table:[16,524288,2] f32,
// W:[64,32] f32, b:[64] f32 -> out:[8,131072,64] f32.

#define NLEVELS 16
#define TSIZE   (1u << 19)
#define TMASK   (TSIZE - 1u)
#define HP1     2654435761u
#define HP2     805459861u

// scale_l = f32(16*1.5^l - 1) computed exactly in double.
__constant__ float cScales[NLEVELS] = {
    15.0f, 23.0f, 35.0f, 53.0f, 80.0f, 120.5f, 181.25f, 272.375f,
    409.0625f, 614.09375f, 921.640625f, 1382.9609375f,
    2074.94140625f, 3112.912109375f, 4669.8681640625f, 7005.30224609375f };

__device__ __forceinline__ uint32_t umin32(uint32_t a, uint32_t b) { return a < b ? a : b; }

// packed fp32x2 fma: d = a*b + d (elementwise, exact fp32)
__device__ __forceinline__ void fma2(unsigned long long& d,
                                     unsigned long long a,
                                     unsigned long long b) {
    asm("fma.rn.f32x2 %0, %1, %2, %0;" : "+l"(d) : "l"(a), "l"(b));
}
__device__ __forceinline__ float2 u2f(unsigned long long v) {
    float2 r;
    asm("mov.b64 {%0, %1}, %2;" : "=f"(r.x), "=f"(r.y) : "l"(v));
    return r;
}

// One hashed level gather+interp. Returns (a0,a1).
__device__ __forceinline__ float2 hashed_level(const float4* __restrict__ tl4,
                                               const float2* __restrict__ tl2,
                                               float xn, float yn, float zn, float s)
{
    const float px = __fadd_rn(__fmul_rn(xn, s), 0.5f);
    const float py = __fadd_rn(__fmul_rn(yn, s), 0.5f);
    const float pz = __fadd_rn(__fmul_rn(zn, s), 0.5f);
    const float fx0 = floorf(px), fy0 = floorf(py), fz0 = floorf(pz);
    const float fx = __fadd_rn(px, -fx0);
    const float fy = __fadd_rn(py, -fy0);
    const float fz = __fadd_rn(pz, -fz0);
    const uint32_t x0 = (uint32_t)fx0;
    const uint32_t y0 = (uint32_t)fy0;
    const uint32_t z0 = (uint32_t)fz0;

    const float wx0 = 1.0f - fx, wx1 = fx;
    const float wy0 = 1.0f - fy, wy1 = fy;
    const float wz0 = 1.0f - fz, wz1 = fz;

    const uint32_t hy0 = y0 * HP1;
    const uint32_t hy1 = hy0 + HP1;
    const uint32_t hz0 = z0 * HP2;
    const uint32_t hz1 = hz0 + HP2;
    const uint32_t x1  = x0 + 1u;
    const bool xodd = (x0 & 1u) != 0u;

    const uint32_t hyz[4] = { hy0 ^ hz0, hy0 ^ hz1, hy1 ^ hz0, hy1 ^ hz1 };
    const float    wyz[4] = { wy0 * wz0, wy0 * wz1, wy1 * wz0, wy1 * wz1 };

    uint32_t i0s[4];
    #pragma unroll
    for (int r = 0; r < 4; ++r) i0s[r] = (x0 ^ hyz[r]) & TMASK;

    float4 v4[4];
    #pragma unroll
    for (int r = 0; r < 4; ++r) v4[r] = __ldg(tl4 + (i0s[r] >> 1));

    float2 vb[4];
    if (xodd) {
        #pragma unroll
        for (int r = 0; r < 4; ++r)
            vb[r] = __ldg(tl2 + ((x1 ^ hyz[r]) & TMASK));
    }

    float a0 = 0.0f, a1 = 0.0f;
    #pragma unroll
    for (int r = 0; r < 4; ++r) {
        const bool hi = (i0s[r] & 1u) != 0u;
        const float c0x = hi ? v4[r].z : v4[r].x;
        const float c0y = hi ? v4[r].w : v4[r].y;
        const float ox  = hi ? v4[r].x : v4[r].z;
        const float oy  = hi ? v4[r].y : v4[r].w;
        const float c1x = xodd ? vb[r].x : ox;
        const float c1y = xodd ? vb[r].y : oy;

        const float w0 = wx0 * wyz[r];
        const float w1 = wx1 * wyz[r];
        a0 = fmaf(w0, c0x, a0);
        a1 = fmaf(w0, c0y, a1);
        a0 = fmaf(w1, c1x, a0);
        a1 = fmaf(w1, c1y, a1);
    }
    return make_float2(a0, a1);
}

__global__ __launch_bounds__(128, 5)
void hashgrid_fused_kernel(const float* __restrict__ x,
                           const float* __restrict__ table,
                           const float* __restrict__ W,
                           const float* __restrict__ bias,
                           float* __restrict__ out,
                           int P)
{
    // enc staging: point-major float4 (levels 2k,2k+1), stride 9 float4.
    __shared__ float4 sEnc[128 * 9];
    // W staged once per block: row r at sW4[r*9 + q] (pad 1 float4).
    __shared__ float4 sW4[64 * 9];
    __shared__ float  sB[64];

    const int tid = threadIdx.x;

    // ---- cooperative coalesced W/b load; sync now so warps enter the
    //      matmul phase staggered ----
    {
        const float4* __restrict__ Wg = reinterpret_cast<const float4*>(W);
        #pragma unroll
        for (int i = 0; i < 4; ++i) {
            const int g = tid + 128 * i;
            sW4[(g >> 3) * 9 + (g & 7)] = __ldg(Wg + g);
        }
        if (tid < 64) sB[tid] = __ldg(bias + tid);
    }
    __syncthreads();

    const int p  = blockIdx.x * 128 + tid;
    const int pc = (p < P) ? p : (P - 1);

    const float xn = __fmul_rn(__fadd_rn(x[3 * pc + 0], 1.0f), 0.5f);
    const float yn = __fmul_rn(__fadd_rn(x[3 * pc + 1], 1.0f), 0.5f);
    const float zn = __fmul_rn(__fadd_rn(x[3 * pc + 2], 1.0f), 0.5f);

    const float2* __restrict__ tbl2 = reinterpret_cast<const float2*>(table);
    const float4* __restrict__ tbl4 = reinterpret_cast<const float4*>(table);

    // ---- dense levels 0..3 (fully unrolled, compile-time res) ----
    {
        const uint32_t RES_D[4] = { 16u, 24u, 36u, 54u };
        const float    SC_D[4]  = { 15.0f, 23.0f, 35.0f, 53.0f };
        float keep0 = 0.0f, keep1 = 0.0f;
        #pragma unroll
        for (int l = 0; l < 4; ++l) {
            const float s  = SC_D[l];
            const float px = __fadd_rn(__fmul_rn(xn, s), 0.5f);
            const float py = __fadd_rn(__fmul_rn(yn, s), 0.5f);
            const float pz = __fadd_rn(__fmul_rn(zn, s), 0.5f);
            const float fx0 = floorf(px), fy0 = floorf(py), fz0 = floorf(pz);
            const float fx = __fadd_rn(px, -fx0);
            const float fy = __fadd_rn(py, -fy0);
            const float fz = __fadd_rn(pz, -fz0);
            const uint32_t x0 = (uint32_t)fx0;
            const uint32_t y0 = (uint32_t)fy0;
            const uint32_t z0 = (uint32_t)fz0;

            const float wx0 = 1.0f - fx, wx1 = fx;
            const float wy0 = 1.0f - fy, wy1 = fy;
            const float wz0 = 1.0f - fz, wz1 = fz;

            const uint32_t R   = RES_D[l];
            const uint32_t cx0 = umin32(x0, R - 1u);
            const bool d1      = (x0 < R - 1u);
            const bool xodd    = (x0 & 1u) != 0u;
            const uint32_t iy0 = umin32(y0,      R - 1u) * R;
            const uint32_t iy1 = umin32(y0 + 1u, R - 1u) * R;
            const uint32_t iz0 = umin32(z0,      R - 1u) * (R * R);
            const uint32_t iz1 = umin32(z0 + 1u, R - 1u) * (R * R);

            const uint32_t byz[4] = { iy0 + iz0, iy0 + iz1, iy1 + iz0, iy1 + iz1 };
            const float    wyz[4] = { wy0 * wz0, wy0 * wz1, wy1 * wz0, wy1 * wz1 };

            const float2* tl2 = tbl2 + (size_t)l * TSIZE;
            const float4* tl4 = tbl4 + (size_t)l * (TSIZE / 2);

            uint32_t i0s[4];
            #pragma unroll
            for (int r = 0; r < 4; ++r) i0s[r] = cx0 + byz[r];

            float4 v4[4];
            #pragma unroll
            for (int r = 0; r < 4; ++r) v4[r] = __ldg(tl4 + (i0s[r] >> 1));

            const bool need2 = d1 && xodd;
            float2 vb[4];
            if (need2) {
                #pragma unroll
                for (int r = 0; r < 4; ++r) vb[r] = __ldg(tl2 + (i0s[r] + 1u));
            }

            float a0 = 0.0f, a1 = 0.0f;
            #pragma unroll
            for (int r = 0; r < 4; ++r) {
                const bool hi = (i0s[r] & 1u) != 0u;
                const float c0x = hi ? v4[r].z : v4[r].x;
                const float c0y = hi ? v4[r].w : v4[r].y;
                const float ox  = hi ? vb[r].x : v4[r].z;
                const float oy  = hi ? vb[r].y : v4[r].w;
                const float c1x = d1 ? ox : c0x;
                const float c1y = d1 ? oy : c0y;

                const float w0 = wx0 * wyz[r];
                const float w1 = wx1 * wyz[r];
                a0 = fmaf(w0, c0x, a0);
                a1 = fmaf(w0, c0y, a1);
                a0 = fmaf(w1, c1x, a0);
                a1 = fmaf(w1, c1y, a1);
            }
            if ((l & 1) == 0) { keep0 = a0; keep1 = a1; }
            else sEnc[tid * 9 + (l >> 1)] = make_float4(keep0, keep1, a0, a1);
        }
    }

    // ---- hashed levels 4..15: rolled loop over 6 level-pairs (low regs) ----
    #pragma unroll 1
    for (int lp = 2; lp < 8; ++lp) {
        const int l0 = 2 * lp;
        const float2 rA = hashed_level(tbl4 + (size_t)l0 * (TSIZE / 2),
                                       tbl2 + (size_t)l0 * TSIZE,
                                       xn, yn, zn, cScales[l0]);
        const float2 rB = hashed_level(tbl4 + (size_t)(l0 + 1) * (TSIZE / 2),
                                       tbl2 + (size_t)(l0 + 1) * TSIZE,
                                       xn, yn, zn, cScales[l0 + 1]);
        sEnc[tid * 9 + lp] = make_float4(rA.x, rA.y, rB.x, rB.y);
    }

    __syncwarp();   // sEnc is per-warp

    // ---- Linear(32 -> 64), packed fp32x2 FMA ----
    const int lane  = tid & 31;
    const int wbase = tid & ~31;
    const int gbase = blockIdx.x * 128 + wbase;

    const ulonglong2* __restrict__ sWp = reinterpret_cast<const ulonglong2*>(sW4);
    ulonglong2 wa[8], wb[8];
    #pragma unroll
    for (int q = 0; q < 8; ++q) {
        wa[q] = sWp[lane * 9 + q];
        wb[q] = sWp[(lane + 32) * 9 + q];
    }
    const float bA = sB[lane];
    const float bB = sB[lane + 32];

    #pragma unroll 1
    for (int q = 0; q < 32; ++q) {
        const ulonglong2* e =
            reinterpret_cast<const ulonglong2*>(&sEnc[(wbase + q) * 9]);
        unsigned long long A0 = 0ull, A1 = 0ull, B0 = 0ull, B1 = 0ull;
        #pragma unroll
        for (int k = 0; k < 8; ++k) {
            const ulonglong2 ev = e[k];        // uniform LDS.128 broadcast
            fma2(A0, ev.x, wa[k].x);
            fma2(A1, ev.y, wa[k].y);
            fma2(B0, ev.x, wb[k].x);
            fma2(B1, ev.y, wb[k].y);
        }
        const float2 fa0 = u2f(A0), fa1 = u2f(A1);
        const float2 fb0 = u2f(B0), fb1 = u2f(B1);
        const float aA = bA + fa0.x + fa0.y + fa1.x + fa1.y;
        const float aB = bB + fb0.x + fb0.y + fb1.x + fb1.y;

        const int gp = gbase + q;
        if (gp < P) {
            out[(size_t)gp * 64 + lane]      = aA;     // 128B coalesced
            out[(size_t)gp * 64 + 32 + lane] = aB;     // 128B coalesced
        }
    }
}

extern "C" void kernel_launch(void* const* d_in, const int* in_sizes, int n_in,
                              void* d_out, int out_size)
{
    const float* x     = (const float*)d_in[0];
    const float* table = (const float*)d_in[1];
    const float* W     = (const float*)d_in[2];
    const float* b     = (const float*)d_in[3];
    float* out = (float*)d_out;

    const int P    = in_sizes[0] / 3;          // 1,048,576 points
    const int grid = (P + 127) / 128;
    hashgrid_fused_kernel<<<grid, 128>>>(x, table, W, b, out, P);
}